// round 6
// baseline (speedup 1.0000x reference)
#include <cuda_runtime.h>

#define BT 8192
#define T1 50
#define T2 100

#define G1 32
#define G2 16
#define HB_P 68     // 68 mod 32 = 4 -> conflict-free lane-strided rows, 272B = 16B-aligned
#define GA_P 260    // gate buffer row pad
#define WT_P 257    // transposed wih rows: [k][g], 257 mod 32 = 1 -> conflict-free staging

// inter-kernel scratch: layer1 output sequence [B][T1][128]
static __device__ float g_seq1[BT * T1 * 128];

__device__ __forceinline__ float fsig(float x) {
    return __fdividef(1.f, 1.f + __expf(-x));
}
__device__ __forceinline__ float ftanh_(float x) {
    float e = __expf(-2.f * fabsf(x));
    float r = __fdividef(1.f - e, 1.f + e);
    return copysignf(r, x);
}
__device__ __forceinline__ float dot4acc(float4 w, float4 h, float a) {
    a = fmaf(w.x, h.x, a); a = fmaf(w.y, h.y, a);
    a = fmaf(w.z, h.z, a); return fmaf(w.w, h.w, a);
}

// ---------------------------------------------------------------------------
// Kernel 1: fc1 + bidirectional LSTM layer 1 (input dim 1) -> g_seq1
// One CTA = G1 samples, 256 threads = 256 gates. Whh row in registers.
// (unchanged: ~76% of its FMA roofline already)
// ---------------------------------------------------------------------------
__global__ __launch_bounds__(256, 2)
void k_layer1(const float* __restrict__ x,
              const float* __restrict__ fc1_w, const float* __restrict__ fc1_b,
              const float* __restrict__ wih_f, const float* __restrict__ whh_f, const float* __restrict__ b_f,
              const float* __restrict__ wih_b, const float* __restrict__ whh_b, const float* __restrict__ b_b)
{
    extern __shared__ float sm[];
    float* gact  = sm;                    // G1*GA_P
    float* hbuf  = gact + G1 * GA_P;      // G1*HB_P
    float* h1buf = hbuf + G1 * HB_P;      // G1*T1

    const int tid  = threadIdx.x;
    const int base = blockIdx.x * G1;
    const int g    = tid;
    const int j    = tid & 63, q = tid >> 6;

    // fc1: h1[s][t] = x[s] . fc1_w[t] + fc1_b[t]
    for (int idx = tid; idx < G1 * T1; idx += 256) {
        int s = idx / T1, t = idx - s * T1;
        const float* xr = x + (base + s) * 20;
        const float* wr = fc1_w + t * 20;
        float acc = fc1_b[t];
        #pragma unroll
        for (int i = 0; i < 20; i++) acc = fmaf(xr[i], wr[i], acc);
        h1buf[s * T1 + t] = acc;
    }

    for (int d = 0; d < 2; d++) {
        const float* whh = d ? whh_b : whh_f;
        const float* wih = d ? wih_b : wih_f;
        const float* bg  = d ? b_b   : b_f;

        __syncthreads();
        for (int idx = tid; idx < G1 * HB_P; idx += 256) hbuf[idx] = 0.f;

        // weight-stationary: this thread's Whh row in registers
        float4 wv[16];
        const float4* wgp = (const float4*)(whh + g * 64);
        #pragma unroll
        for (int kc = 0; kc < 16; kc++) wv[kc] = __ldg(wgp + kc);
        const float wihg = __ldg(wih + g);
        const float bsg  = __ldg(bg + g);

        float c_reg[8];
        #pragma unroll
        for (int i = 0; i < 8; i++) c_reg[i] = 0.f;
        __syncthreads();

        const bool tanh_gate = ((g >> 6) == 2);

        for (int tt = 0; tt < T1; tt++) {
            const int t = d ? (T1 - 1 - tt) : tt;

            for (int sg = 0; sg < G1; sg += 2) {
                float a0 = fmaf(h1buf[(sg + 0) * T1 + t], wihg, bsg);
                float a1 = fmaf(h1buf[(sg + 1) * T1 + t], wihg, bsg);
                #pragma unroll
                for (int kc = 0; kc < 16; kc++) {
                    float4 w4 = wv[kc];
                    float4 h0 = *(const float4*)(hbuf + (sg + 0) * HB_P + kc * 4);
                    float4 h1 = *(const float4*)(hbuf + (sg + 1) * HB_P + kc * 4);
                    a0 = dot4acc(w4, h0, a0);
                    a1 = dot4acc(w4, h1, a1);
                }
                gact[(sg + 0) * GA_P + g] = tanh_gate ? ftanh_(a0) : fsig(a0);
                gact[(sg + 1) * GA_P + g] = tanh_gate ? ftanh_(a1) : fsig(a1);
            }
            __syncthreads();

            #pragma unroll
            for (int si = 0; si < 8; si++) {
                const int s = q + si * 4;
                float gi = gact[s * GA_P + j];
                float gf = gact[s * GA_P + 64 + j];
                float gg = gact[s * GA_P + 128 + j];
                float go = gact[s * GA_P + 192 + j];
                float c  = fmaf(gf, c_reg[si], gi * gg);
                c_reg[si] = c;
                float h = go * ftanh_(c);
                hbuf[s * HB_P + j] = h;
                g_seq1[((base + s) * T1 + t) * 128 + d * 64 + j] = h;
            }
            __syncthreads();
        }
    }
}

// ---------------------------------------------------------------------------
// Kernel 2: bidirectional LSTM layer 2 + fc2 + tanh.
// 512 threads: two 256-gate halves, each owning 8 of the 16 samples.
// Input-proj weights transposed in SMEM -> conflict-free, loaded once per step.
// ---------------------------------------------------------------------------
__global__ __launch_bounds__(512, 1)
void k_layer2(const float* __restrict__ wih2_f, const float* __restrict__ whh2_f, const float* __restrict__ b2_f,
              const float* __restrict__ wih2_b, const float* __restrict__ whh2_b, const float* __restrict__ b2_b,
              const float* __restrict__ fc2_w, const float* __restrict__ fc2_b,
              float* __restrict__ out)
{
    extern __shared__ float sm[];
    float* wih_sT = sm;                      // 128*WT_P  (transposed: [k][g])
    float* xgb    = wih_sT + 128 * WT_P;     // G2*GA_P   (cached input projection)
    float* gact   = xgb  + G2 * GA_P;        // G2*GA_P
    float* hbuf   = gact + G2 * GA_P;        // G2*HB_P
    float* inbuf  = hbuf + G2 * HB_P;        // G2*128
    float* outac  = inbuf + G2 * 128;        // G2*T2  (fwd fc2 partial dots)
    float* fc2_s  = outac + G2 * T2;         // 128

    const int tid  = threadIdx.x;
    const int base = blockIdx.x * G2;
    const int g    = tid & 255;            // gate id
    const int half = tid >> 8;             // 0 or 1: which 8 samples
    const int s0   = half * 8;
    const int j    = tid & 63, q = tid >> 6;   // q in 0..7 (state update)
    const int wrp  = tid >> 5, lan = tid & 31; // 16 warps (fc2)

    if (tid < 128) fc2_s[tid] = fc2_w[tid];
    const float fc2b = __ldg(fc2_b);

    for (int d = 0; d < 2; d++) {
        const float* whh = d ? whh2_b : whh2_f;
        const float* wih = d ? wih2_b : wih2_f;
        const float* bg  = d ? b2_b   : b2_f;

        __syncthreads();
        // stage input-projection weights TRANSPOSED: wih_sT[k][g] = wih[g][k]
        // write: lanes have consecutive k at fixed g -> stride WT_P=257 ≡ 1 mod 32 -> conflict-free
        for (int idx = tid; idx < 256 * 128; idx += 512) {
            int gg = idx >> 7, kk = idx & 127;
            wih_sT[kk * WT_P + gg] = wih[idx];
        }
        for (int idx = tid; idx < G2 * HB_P; idx += 512) hbuf[idx] = 0.f;

        // recurrent weights: this thread's Whh row in registers
        float4 wv[16];
        const float4* wgp = (const float4*)(whh + g * 64);
        #pragma unroll
        for (int kc = 0; kc < 16; kc++) wv[kc] = __ldg(wgp + kc);
        const float bsg = __ldg(bg + g);

        float c_reg[2] = {0.f, 0.f};
        __syncthreads();

        const bool tanh_gate = ((g >> 6) == 2);

        for (int tt = 0; tt < T2; tt++) {
            const int t = d ? (T2 - 1 - tt) : tt;

            // first visit of each repeated pair: load input + compute projection
            if ((tt & 1) == 0) {
                const int m = t >> 1;
                for (int idx = tid; idx < G2 * 32; idx += 512) {
                    int s = idx >> 5, i = idx & 31;
                    ((float4*)inbuf)[idx] =
                        ((const float4*)(g_seq1 + ((base + s) * T1 + m) * 128))[i];
                }
                __syncthreads();

                // k-outer, 8-sample accumulators: each weight loaded ONCE,
                // conflict-free scalar LDS; sample vectors are warp-broadcast.
                float a[8];
                #pragma unroll
                for (int ss = 0; ss < 8; ss++) a[ss] = bsg;
                #pragma unroll 4
                for (int k = 0; k < 128; k += 4) {
                    float w0 = wih_sT[(k + 0) * WT_P + g];
                    float w1 = wih_sT[(k + 1) * WT_P + g];
                    float w2 = wih_sT[(k + 2) * WT_P + g];
                    float w3 = wih_sT[(k + 3) * WT_P + g];
                    #pragma unroll
                    for (int ss = 0; ss < 8; ss++) {
                        float4 in4 = *(const float4*)(inbuf + (s0 + ss) * 128 + k);
                        float av = a[ss];
                        av = fmaf(in4.x, w0, av);
                        av = fmaf(in4.y, w1, av);
                        av = fmaf(in4.z, w2, av);
                        a[ss] = fmaf(in4.w, w3, av);
                    }
                }
                #pragma unroll
                for (int ss = 0; ss < 8; ss++)
                    xgb[(s0 + ss) * GA_P + g] = a[ss];   // same-thread reuse only
            }

            // recurrence: gates = xg + Whh @ h   (weights in regs, h broadcast)
            for (int sg = s0; sg < s0 + 8; sg += 2) {
                float a0 = xgb[(sg + 0) * GA_P + g];
                float a1 = xgb[(sg + 1) * GA_P + g];
                #pragma unroll
                for (int kc = 0; kc < 16; kc++) {
                    float4 w4 = wv[kc];
                    float4 h0 = *(const float4*)(hbuf + (sg + 0) * HB_P + kc * 4);
                    float4 h1 = *(const float4*)(hbuf + (sg + 1) * HB_P + kc * 4);
                    a0 = dot4acc(w4, h0, a0);
                    a1 = dot4acc(w4, h1, a1);
                }
                gact[(sg + 0) * GA_P + g] = tanh_gate ? ftanh_(a0) : fsig(a0);
                gact[(sg + 1) * GA_P + g] = tanh_gate ? ftanh_(a1) : fsig(a1);
            }
            __syncthreads();

            // state update: thread (j,q) owns hidden unit j of samples q, q+8
            #pragma unroll
            for (int si = 0; si < 2; si++) {
                const int s = q + si * 8;
                float gi = gact[s * GA_P + j];
                float gf = gact[s * GA_P + 64 + j];
                float gg = gact[s * GA_P + 128 + j];
                float go = gact[s * GA_P + 192 + j];
                float c  = fmaf(gf, c_reg[si], gi * gg);
                c_reg[si] = c;
                hbuf[s * HB_P + j] = go * ftanh_(c);
            }
            __syncthreads();

            // fc2 partial dot: warp wrp owns sample wrp
            {
                const int s = wrp;
                float p = hbuf[s * HB_P + lan]      * fc2_s[d * 64 + lan]
                        + hbuf[s * HB_P + 32 + lan] * fc2_s[d * 64 + 32 + lan];
                #pragma unroll
                for (int o = 16; o > 0; o >>= 1)
                    p += __shfl_down_sync(0xffffffffu, p, o);
                if (lan == 0) {
                    if (d == 0) outac[s * T2 + t] = p;
                    else out[(base + s) * T2 + t] = ftanh_(outac[s * T2 + t] + p + fc2b);
                }
            }
        }
    }
}

// ---------------------------------------------------------------------------
extern "C" void kernel_launch(void* const* d_in, const int* in_sizes, int n_in,
                              void* d_out, int out_size)
{
    const float* x    = (const float*)d_in[0];
    const float* fc1w = (const float*)d_in[1];
    const float* fc1b = (const float*)d_in[2];
    const float* r1wf = (const float*)d_in[3];
    const float* r1hf = (const float*)d_in[4];
    const float* r1bf = (const float*)d_in[5];
    const float* r1wb = (const float*)d_in[6];
    const float* r1hb = (const float*)d_in[7];
    const float* r1bb = (const float*)d_in[8];
    const float* r2wf = (const float*)d_in[9];
    const float* r2hf = (const float*)d_in[10];
    const float* r2bf = (const float*)d_in[11];
    const float* r2wb = (const float*)d_in[12];
    const float* r2hb = (const float*)d_in[13];
    const float* r2bb = (const float*)d_in[14];
    const float* fc2w = (const float*)d_in[15];
    const float* fc2b = (const float*)d_in[16];
    float* out = (float*)d_out;

    const size_t SM1 = (size_t)(G1 * GA_P + G1 * HB_P + G1 * T1) * sizeof(float);
    const size_t SM2 = (size_t)(128 * WT_P + 2 * G2 * GA_P + G2 * HB_P +
                                G2 * 128 + G2 * T2 + 128) * sizeof(float);

    cudaFuncSetAttribute(k_layer1, cudaFuncAttributeMaxDynamicSharedMemorySize, (int)SM1);
    cudaFuncSetAttribute(k_layer2, cudaFuncAttributeMaxDynamicSharedMemorySize, (int)SM2);

    k_layer1<<<BT / G1, 256, SM1>>>(x, fc1w, fc1b, r1wf, r1hf, r1bf, r1wb, r1hb, r1bb);
    k_layer2<<<BT / G2, 512, SM2>>>(r2wf, r2hf, r2bf, r2wb, r2hb, r2bb, fc2w, fc2b, out);
}

// round 8
// speedup vs baseline: 2.4011x; 2.4011x over previous
#include <cuda_runtime.h>
#include <cuda_bf16.h>
#include <cstdint>

#define BT 8192
#define T1 50
#define T2 100
#define G1 32
#define HB_P 68
#define GA_P 260

static __device__ float g_seq1[BT * T1 * 128];
static __device__ uint32_t g_wihf[2 * 16 * 8 * 2 * 4 * 32];   // [d][w][ks][term][r][lane]
static __device__ uint32_t g_whhf[2 * 16 * 4 * 2 * 4 * 32];

__device__ __forceinline__ float fsig(float x) {
    return __fdividef(1.f, 1.f + __expf(-x));
}
__device__ __forceinline__ float ftanh_(float x) {
    float e = __expf(-2.f * fabsf(x));
    float r = __fdividef(1.f - e, 1.f + e);
    return copysignf(r, x);
}
__device__ __forceinline__ float dot4acc(float4 w, float4 h, float a) {
    a = fmaf(w.x, h.x, a); a = fmaf(w.y, h.y, a);
    a = fmaf(w.z, h.z, a); return fmaf(w.w, h.w, a);
}
__device__ __forceinline__ uint32_t pack_bf2(float v0, float v1) {
    __nv_bfloat162 t = __floats2bfloat162_rn(v0, v1);   // lo half = v0
    return *(uint32_t*)&t;
}
// bf16 hi/lo split of a pair, packed
__device__ __forceinline__ void split_pair(float v0, float v1, uint32_t& hi, uint32_t& lo) {
    __nv_bfloat16 h0 = __float2bfloat16_rn(v0), h1 = __float2bfloat16_rn(v1);
    hi = ((uint32_t)*(uint16_t*)&h1 << 16) | *(uint16_t*)&h0;
    lo = pack_bf2(v0 - __bfloat162float(h0), v1 - __bfloat162float(h1));
}
#define MMA(c, a, b0, b1) \
    asm volatile("mma.sync.aligned.m16n8k16.row.col.f32.bf16.bf16.f32 " \
                 "{%0,%1,%2,%3},{%4,%5,%6,%7},{%8,%9},{%0,%1,%2,%3};" \
                 : "+f"((c)[0]), "+f"((c)[1]), "+f"((c)[2]), "+f"((c)[3]) \
                 : "r"((a)[0]), "r"((a)[1]), "r"((a)[2]), "r"((a)[3]), "r"(b0), "r"(b1))

// ===========================================================================
// k_prep: pre-split weights into A-fragment layout (bf16 hi/lo packed pairs)
// frag element (r, lane): row = w*16 + (lane>>2) + (r&1)*8, col = ks*16 + ((r>>1)&1)*8 + (lane&3)*2
// ===========================================================================
__global__ void k_prep(const float* __restrict__ wf, const float* __restrict__ wb,
                       const float* __restrict__ hf, const float* __restrict__ hb)
{
    const int tid = threadIdx.x;
    for (int e = tid; e < 2 * 16 * 8 * 4 * 32; e += 512) {
        int l = e & 31, r = (e >> 5) & 3, ks = (e >> 7) & 7, w = (e >> 10) & 15, d = e >> 14;
        const float* W = d ? wb : wf;
        int row = w * 16 + (l >> 2) + (r & 1) * 8;
        int col = ks * 16 + ((r >> 1) & 1) * 8 + (l & 3) * 2;
        uint32_t hi, lo;
        split_pair(W[row * 128 + col], W[row * 128 + col + 1], hi, lo);
        uint32_t base = (((d * 16 + w) * 8 + ks) * 2) * 128 + r * 32 + l;
        g_wihf[base] = hi; g_wihf[base + 128] = lo;
    }
    for (int e = tid; e < 2 * 16 * 4 * 4 * 32; e += 512) {
        int l = e & 31, r = (e >> 5) & 3, ks = (e >> 7) & 3, w = (e >> 9) & 15, d = e >> 13;
        const float* W = d ? hb : hf;
        int row = w * 16 + (l >> 2) + (r & 1) * 8;
        int col = ks * 16 + ((r >> 1) & 1) * 8 + (l & 3) * 2;
        uint32_t hi, lo;
        split_pair(W[row * 64 + col], W[row * 64 + col + 1], hi, lo);
        uint32_t base = (((d * 16 + w) * 4 + ks) * 2) * 128 + r * 32 + l;
        g_whhf[base] = hi; g_whhf[base + 128] = lo;
    }
}

// ===========================================================================
// Kernel 1: fc1 + BiLSTM layer 1 (input dim 1) -> g_seq1  (FFMA, unchanged)
// ===========================================================================
__global__ __launch_bounds__(256, 2)
void k_layer1(const float* __restrict__ x,
              const float* __restrict__ fc1_w, const float* __restrict__ fc1_b,
              const float* __restrict__ wih_f, const float* __restrict__ whh_f, const float* __restrict__ b_f,
              const float* __restrict__ wih_b, const float* __restrict__ whh_b, const float* __restrict__ b_b)
{
    extern __shared__ float sm[];
    float* gact  = sm;
    float* hbuf  = gact + G1 * GA_P;
    float* h1buf = hbuf + G1 * HB_P;

    const int tid  = threadIdx.x;
    const int base = blockIdx.x * G1;
    const int g    = tid;
    const int j    = tid & 63, q = tid >> 6;

    for (int idx = tid; idx < G1 * T1; idx += 256) {
        int s = idx / T1, t = idx - s * T1;
        const float* xr = x + (base + s) * 20;
        const float* wr = fc1_w + t * 20;
        float acc = fc1_b[t];
        #pragma unroll
        for (int i = 0; i < 20; i++) acc = fmaf(xr[i], wr[i], acc);
        h1buf[s * T1 + t] = acc;
    }

    for (int d = 0; d < 2; d++) {
        const float* whh = d ? whh_b : whh_f;
        const float* wih = d ? wih_b : wih_f;
        const float* bg  = d ? b_b   : b_f;

        __syncthreads();
        for (int idx = tid; idx < G1 * HB_P; idx += 256) hbuf[idx] = 0.f;

        float4 wv[16];
        const float4* wgp = (const float4*)(whh + g * 64);
        #pragma unroll
        for (int kc = 0; kc < 16; kc++) wv[kc] = __ldg(wgp + kc);
        const float wihg = __ldg(wih + g);
        const float bsg  = __ldg(bg + g);

        float c_reg[8];
        #pragma unroll
        for (int i = 0; i < 8; i++) c_reg[i] = 0.f;
        __syncthreads();

        const bool tanh_gate = ((g >> 6) == 2);

        for (int tt = 0; tt < T1; tt++) {
            const int t = d ? (T1 - 1 - tt) : tt;
            for (int sg = 0; sg < G1; sg += 2) {
                float a0 = fmaf(h1buf[(sg + 0) * T1 + t], wihg, bsg);
                float a1 = fmaf(h1buf[(sg + 1) * T1 + t], wihg, bsg);
                #pragma unroll
                for (int kc = 0; kc < 16; kc++) {
                    float4 w4 = wv[kc];
                    float4 h0 = *(const float4*)(hbuf + (sg + 0) * HB_P + kc * 4);
                    float4 h1 = *(const float4*)(hbuf + (sg + 1) * HB_P + kc * 4);
                    a0 = dot4acc(w4, h0, a0);
                    a1 = dot4acc(w4, h1, a1);
                }
                gact[(sg + 0) * GA_P + g] = tanh_gate ? ftanh_(a0) : fsig(a0);
                gact[(sg + 1) * GA_P + g] = tanh_gate ? ftanh_(a1) : fsig(a1);
            }
            __syncthreads();
            #pragma unroll
            for (int si = 0; si < 8; si++) {
                const int s = q + si * 4;
                float gi = gact[s * GA_P + j];
                float gf = gact[s * GA_P + 64 + j];
                float gg = gact[s * GA_P + 128 + j];
                float go = gact[s * GA_P + 192 + j];
                float c  = fmaf(gf, c_reg[si], gi * gg);
                c_reg[si] = c;
                float h = go * ftanh_(c);
                hbuf[s * HB_P + j] = h;
                g_seq1[((base + s) * T1 + t) * 128 + d * 64 + j] = h;
            }
            __syncthreads();
        }
    }
}

// ===========================================================================
// k_layer2: BiLSTM layer 2 on mma.sync (bf16 hi/lo 3-term) + fc2 + tanh
// CTA = 64 samples, 16 warps; warp w = gates [w*16, w*16+16) x 64 samples.
// SMEM (bytes): xT hi/lo (rows 136 halfs), hT hi/lo (rows 72 halfs),
//               gact fp32 [64][260], hbuf [64][68], outac [64][100]
// ===========================================================================
#define XT_HI 0
#define XT_LO 17408
#define HT_HI 34816
#define HT_LO 44032
#define GACTO 53248
#define HBUFO 119808
#define OUTAO 137216
#define L2_SM 162816

__global__ __launch_bounds__(512, 1)
void k_layer2(const float* __restrict__ b2_f, const float* __restrict__ b2_b,
              const float* __restrict__ fc2_w, const float* __restrict__ fc2_b,
              float* __restrict__ out)
{
    extern __shared__ char smc[];
    uint32_t* xth = (uint32_t*)(smc + XT_HI);
    uint32_t* xtl = (uint32_t*)(smc + XT_LO);
    uint32_t* hth = (uint32_t*)(smc + HT_HI);
    uint32_t* htl = (uint32_t*)(smc + HT_LO);
    float*    ga  = (float*)(smc + GACTO);
    float*    hbf = (float*)(smc + HBUFO);
    float*    oa  = (float*)(smc + OUTAO);

    const int tid = threadIdx.x;
    const int w   = tid >> 5, lid = tid & 31;
    const int grp = lid >> 2, tk = lid & 3;
    const int j = tid & 63, q = tid >> 6;
    const int blk = blockIdx.x;
    const float fc2bv = __ldg(fc2_b);

    for (int d = 0; d < 2; d++) {
        const float* bg = d ? b2_b : b2_f;
        const float bv0 = __ldg(&bg[w * 16 + grp]);
        const float bv1 = __ldg(&bg[w * 16 + grp + 8]);
        const float fwa = __ldg(&fc2_w[d * 64 + lid]);
        const float fwb = __ldg(&fc2_w[d * 64 + 32 + lid]);

        // resident Whh A-fragments: [ks][term][r]
        uint32_t wa[32];
        {
            const uint32_t* hp = g_whhf + (d * 16 + w) * 4 * 256 + lid;
            #pragma unroll
            for (int ks = 0; ks < 4; ks++)
                #pragma unroll
                for (int tm = 0; tm < 2; tm++)
                    #pragma unroll
                    for (int r = 0; r < 4; r++)
                        wa[(ks * 2 + tm) * 4 + r] = __ldg(hp + (ks * 2 + tm) * 128 + r * 32);
        }

        __syncthreads();
        for (int p = tid; p < 4608; p += 512) hth[p] = 0u;   // hT hi+lo contiguous
        float c8[8];
        #pragma unroll
        for (int i = 0; i < 8; i++) c8[i] = 0.f;
        float xg[32], cc[8][4];
        __syncthreads();

        for (int tt = 0; tt < T2; tt++) {
            const int t = d ? (T2 - 1 - tt) : tt;

            if ((tt & 1) == 0) {
                // stage x chunk [64 samples][128] -> bf16 hi/lo xT
                const int m = t >> 1;
                {
                    int s = tid >> 3, f0 = (tid & 7) * 16;
                    const float4* xr = (const float4*)(g_seq1 +
                        ((size_t)(blk * 64 + s) * T1 + m) * 128 + f0);
                    int wbase = s * 68 + (f0 >> 1);
                    #pragma unroll
                    for (int i = 0; i < 4; i++) {
                        float4 v = __ldg(xr + i);
                        uint32_t h0, l0, h1, l1;
                        split_pair(v.x, v.y, h0, l0);
                        split_pair(v.z, v.w, h1, l1);
                        xth[wbase + i * 2] = h0; xth[wbase + i * 2 + 1] = h1;
                        xtl[wbase + i * 2] = l0; xtl[wbase + i * 2 + 1] = l1;
                    }
                }
                __syncthreads();
                // proj: cc = bias + Wih @ x  (3-term)
                #pragma unroll
                for (int n = 0; n < 8; n++) {
                    cc[n][0] = bv0; cc[n][1] = bv0; cc[n][2] = bv1; cc[n][3] = bv1;
                }
                const uint32_t* wp = g_wihf + (d * 16 + w) * 8 * 256 + lid;
                for (int ks = 0; ks < 8; ks++) {
                    uint32_t ah[4], al[4];
                    #pragma unroll
                    for (int r = 0; r < 4; r++) {
                        ah[r] = __ldg(wp + ks * 256 + r * 32);
                        al[r] = __ldg(wp + ks * 256 + 128 + r * 32);
                    }
                    #pragma unroll
                    for (int n = 0; n < 8; n++) {
                        int wd = (n * 8 + grp) * 68 + ks * 8 + tk;
                        uint32_t bh0 = xth[wd], bh1 = xth[wd + 4];
                        uint32_t bl0 = xtl[wd], bl1 = xtl[wd + 4];
                        MMA(cc[n], ah, bh0, bh1);
                        MMA(cc[n], ah, bl0, bl1);
                        MMA(cc[n], al, bh0, bh1);
                    }
                }
                #pragma unroll
                for (int n = 0; n < 8; n++)
                    #pragma unroll
                    for (int r = 0; r < 4; r++) xg[n * 4 + r] = cc[n][r];
            } else {
                #pragma unroll
                for (int n = 0; n < 8; n++)
                    #pragma unroll
                    for (int r = 0; r < 4; r++) cc[n][r] = xg[n * 4 + r];
            }

            // recurrence: cc += Whh @ h  (3-term, A resident)
            #pragma unroll
            for (int ks = 0; ks < 4; ks++) {
                #pragma unroll
                for (int n = 0; n < 8; n++) {
                    int wd = (n * 8 + grp) * 36 + ks * 8 + tk;
                    uint32_t bh0 = hth[wd], bh1 = hth[wd + 4];
                    uint32_t bl0 = htl[wd], bl1 = htl[wd + 4];
                    MMA(cc[n], &wa[(ks * 2 + 0) * 4], bh0, bh1);
                    MMA(cc[n], &wa[(ks * 2 + 0) * 4], bl0, bl1);
                    MMA(cc[n], &wa[(ks * 2 + 1) * 4], bh0, bh1);
                }
            }

            // scatter gates to gact[sample][gate]
            #pragma unroll
            for (int n = 0; n < 8; n++) {
                int s0 = n * 8 + 2 * tk, gcol = w * 16 + grp;
                ga[s0 * 260 + gcol]           = cc[n][0];
                ga[(s0 + 1) * 260 + gcol]     = cc[n][1];
                ga[s0 * 260 + gcol + 8]       = cc[n][2];
                ga[(s0 + 1) * 260 + gcol + 8] = cc[n][3];
            }
            __syncthreads();

            // state update: thread (j,q) -> samples s = q + 8*si
            #pragma unroll
            for (int si = 0; si < 8; si++) {
                const int s = q + si * 8;
                float gi = ga[s * 260 + j],       gf = ga[s * 260 + 64 + j];
                float gg = ga[s * 260 + 128 + j], go = ga[s * 260 + 192 + j];
                float c = fmaf(fsig(gf), c8[si], fsig(gi) * ftanh_(gg));
                c8[si] = c;
                float h = fsig(go) * ftanh_(c);
                hbf[s * 68 + j] = h;
                __nv_bfloat16 hh = __float2bfloat16_rn(h);
                __nv_bfloat16 hl = __float2bfloat16_rn(h - __bfloat162float(hh));
                ((__nv_bfloat16*)hth)[s * 72 + j] = hh;
                ((__nv_bfloat16*)htl)[s * 72 + j] = hl;
            }
            __syncthreads();

            // fc2: warp w owns samples w*4 .. w*4+3
            #pragma unroll
            for (int si2 = 0; si2 < 4; si2++) {
                const int s = w * 4 + si2;
                float pm = hbf[s * 68 + lid] * fwa + hbf[s * 68 + 32 + lid] * fwb;
                #pragma unroll
                for (int o = 16; o > 0; o >>= 1)
                    pm += __shfl_down_sync(0xffffffffu, pm, o);
                if (lid == 0) {
                    if (d == 0) oa[s * 100 + t] = pm;
                    else out[(size_t)(blk * 64 + s) * T2 + t] = ftanh_(oa[s * 100 + t] + pm + fc2bv);
                }
            }
        }
    }
}

// ---------------------------------------------------------------------------
extern "C" void kernel_launch(void* const* d_in, const int* in_sizes, int n_in,
                              void* d_out, int out_size)
{
    const float* x    = (const float*)d_in[0];
    const float* fc1w = (const float*)d_in[1];
    const float* fc1b = (const float*)d_in[2];
    const float* r1wf = (const float*)d_in[3];
    const float* r1hf = (const float*)d_in[4];
    const float* r1bf = (const float*)d_in[5];
    const float* r1wb = (const float*)d_in[6];
    const float* r1hb = (const float*)d_in[7];
    const float* r1bb = (const float*)d_in[8];
    const float* r2wf = (const float*)d_in[9];
    const float* r2hf = (const float*)d_in[10];
    const float* r2bf = (const float*)d_in[11];
    const float* r2wb = (const float*)d_in[12];
    const float* r2hb = (const float*)d_in[13];
    const float* r2bb = (const float*)d_in[14];
    const float* fc2w = (const float*)d_in[15];
    const float* fc2b = (const float*)d_in[16];
    float* out = (float*)d_out;

    const size_t SM1 = (size_t)(G1 * GA_P + G1 * HB_P + G1 * T1) * sizeof(float);

    cudaFuncSetAttribute(k_layer1, cudaFuncAttributeMaxDynamicSharedMemorySize, (int)SM1);
    cudaFuncSetAttribute(k_layer2, cudaFuncAttributeMaxDynamicSharedMemorySize, L2_SM);

    k_prep<<<1, 512>>>(r2wf, r2wb, r2hf, r2hb);
    k_layer1<<<BT / G1, 256, SM1>>>(x, fc1w, fc1b, r1wf, r1hf, r1bf, r1wb, r1hb, r1bb);
    k_layer2<<<128, 512, L2_SM>>>(r2bf, r2bb, fc2w, fc2b, out);
}